// round 4
// baseline (speedup 1.0000x reference)
#include <cuda_runtime.h>
#include <cuda_bf16.h>
#include <math.h>
#include <stdint.h>

#define BB 4
#define TT 2048
#define CC 1024
#define HH 16
#define DD 64
#define EPS 1.1920929e-07f

// ---------------------------------------------------------------------------
// Scratch (allocation-free rule)
// ---------------------------------------------------------------------------
__device__ float g_q[BB * TT * CC];
__device__ float g_k[BB * TT * CC];
__device__ float g_v[BB * TT * CC];
__device__ float g_y[BB * TT * CC];

// ---------------------------------------------------------------------------
// tf32 helpers
// ---------------------------------------------------------------------------
__device__ __forceinline__ float to_tf32(float x) {
    uint32_t u;
    asm("cvt.rna.tf32.f32 %0, %1;" : "=r"(u) : "f"(x));
    return __uint_as_float(u);
}

__device__ __forceinline__ void mma_tf32(float* c, const uint32_t* a, const uint32_t* b) {
    asm volatile(
        "mma.sync.aligned.m16n8k8.row.col.f32.tf32.tf32.f32 "
        "{%0,%1,%2,%3}, {%4,%5,%6,%7}, {%8,%9}, {%0,%1,%2,%3};"
        : "+f"(c[0]), "+f"(c[1]), "+f"(c[2]), "+f"(c[3])
        : "r"(a[0]), "r"(a[1]), "r"(a[2]), "r"(a[3]), "r"(b[0]), "r"(b[1]));
}

// Fragment-layout smem:
//  A-frag (m16k8 tile): addr = ((mtile*KT + kchunk)*32 + lane)*4 + reg
//    element (r,c): lane=(r%8)*4 + c%4, reg=((r%16)>=8) + 2*((c%8)>=4)
//  B-frag (n8k8 tile):  addr = ((ntile*KT + kchunk)*32 + lane)*2 + reg
//    element (n,c): lane=(n%8)*4 + c%4, reg=((c%8)>=4)
// Mainloop: A = one LDS.128, B = one LDS.64, both conflict-free.

// ---------------------------------------------------------------------------
// GEMM NT (tf32 MMA): C[m,n] = sum_k A[m,k] * W[n,k]
// 128x128x16 tile, 256 threads (8 warps 2x4), warp tile 64x32.
// Double-buffered fragment-layout smem + register prefetch.
// blockIdx.z selects among up to 3 (W, C) pairs (fused QKV).
// ---------------------------------------------------------------------------
#define GBM 128
#define GBN 128
#define GBK 16

__global__ __launch_bounds__(256, 2) void gemm3_tf32(
    const float* __restrict__ A,
    const float* __restrict__ W0, const float* __restrict__ W1, const float* __restrict__ W2,
    float* __restrict__ C0, float* __restrict__ C1, float* __restrict__ C2,
    int M, int N, int K)
{
    __shared__ float As[2][2048];   // 8 mtiles x 2 kchunks x 32 lanes x 4 regs
    __shared__ float Ws[2][2048];   // 16 ntiles x 2 kchunks x 32 lanes x 2 regs

    const float* W = blockIdx.z == 0 ? W0 : (blockIdx.z == 1 ? W1 : W2);
    float* Cout    = blockIdx.z == 0 ? C0 : (blockIdx.z == 1 ? C1 : C2);

    const int tid = threadIdx.x;
    const int wid = tid >> 5;
    const int lane = tid & 31;
    const int wm = wid & 1;        // 0..1 (64-row slab)
    const int wn = wid >> 1;       // 0..3 (32-col slab)
    const int g = lane >> 2;
    const int tg = lane & 3;

    const int m0 = blockIdx.y * GBM;
    const int n0 = blockIdx.x * GBN;

    const int lr = tid >> 2;          // 0..63
    const int lc = (tid & 3) << 2;    // 0,4,8,12

    const float* Arow0 = &A[(size_t)(m0 + lr) * K + lc];
    const float* Arow1 = &A[(size_t)(m0 + lr + 64) * K + lc];
    const float* Wrow0 = &W[(size_t)(n0 + lr) * K + lc];
    const float* Wrow1 = &W[(size_t)(n0 + lr + 64) * K + lc];

    // staging destinations (r, lc fixed per thread)
    const int kch = lc >> 3;                 // 0 or 1
    const int regkA = (lc & 4) >> 1;         // 0 or 2
    const int regkB = (lc & 4) >> 2;         // 0 or 1

    float acc[4][4][4] = {};

    auto stageA = [&](int buf, int r, float4 v) {
        int reg = (((r & 15) >= 8) ? 1 : 0) + regkA;
        float* base = &As[buf][(((r >> 4) * 2 + kch) * 32 + (r & 7) * 4) * 4 + reg];
        base[0]  = to_tf32(v.x); base[4]  = to_tf32(v.y);
        base[8]  = to_tf32(v.z); base[12] = to_tf32(v.w);
    };
    auto stageW = [&](int buf, int n, float4 v) {
        float* base = &Ws[buf][(((n >> 3) * 2 + kch) * 32 + (n & 7) * 4) * 2 + regkB];
        base[0] = to_tf32(v.x); base[2] = to_tf32(v.y);
        base[4] = to_tf32(v.z); base[6] = to_tf32(v.w);
    };

    // preload tile 0
    stageA(0, lr,      *(const float4*)Arow0);
    stageA(0, lr + 64, *(const float4*)Arow1);
    stageW(0, lr,      *(const float4*)Wrow0);
    stageW(0, lr + 64, *(const float4*)Wrow1);
    __syncthreads();

    const int nt = K / GBK;
    for (int kt = 0; kt < nt; kt++) {
        const int cur = kt & 1;
        const bool has = (kt + 1) < nt;
        float4 a0, a1, w0, w1;
        if (has) {
            const int k1 = (kt + 1) * GBK;
            a0 = *(const float4*)(Arow0 + k1);
            a1 = *(const float4*)(Arow1 + k1);
            w0 = *(const float4*)(Wrow0 + k1);
            w1 = *(const float4*)(Wrow1 + k1);
        }

        #pragma unroll
        for (int kc = 0; kc < 2; kc++) {
            uint4 af[4]; uint2 bf[4];
            #pragma unroll
            for (int mi = 0; mi < 4; mi++)
                af[mi] = *(const uint4*)&As[cur][((wm * 8 + mi * 2 + kc) * 32 + lane) * 4];
            #pragma unroll
            for (int ni = 0; ni < 4; ni++)
                bf[ni] = *(const uint2*)&Ws[cur][(((wn * 4 + ni) * 2 + kc) * 32 + lane) * 2];
            #pragma unroll
            for (int mi = 0; mi < 4; mi++)
                #pragma unroll
                for (int ni = 0; ni < 4; ni++)
                    mma_tf32(acc[mi][ni], (const uint32_t*)&af[mi], (const uint32_t*)&bf[ni]);
        }

        if (has) {
            const int nb = cur ^ 1;
            stageA(nb, lr, a0);
            stageA(nb, lr + 64, a1);
            stageW(nb, lr, w0);
            stageW(nb, lr + 64, w1);
        }
        __syncthreads();
    }

    #pragma unroll
    for (int mi = 0; mi < 4; mi++) {
        int r = m0 + wm * 64 + mi * 16 + g;
        #pragma unroll
        for (int ni = 0; ni < 4; ni++) {
            int c = n0 + wn * 32 + ni * 8 + tg * 2;
            *(float2*)&Cout[(size_t)r * N + c] =
                make_float2(acc[mi][ni][0], acc[mi][ni][1]);
            *(float2*)&Cout[(size_t)(r + 8) * N + c] =
                make_float2(acc[mi][ni][2], acc[mi][ni][3]);
        }
    }
}

// ---------------------------------------------------------------------------
// RoPE (concat-half) + RMSnorm, in-place on q,k. 8 rows per 256-thread block.
// ---------------------------------------------------------------------------
__global__ __launch_bounds__(256) void rope_rms(
    float* __restrict__ q, float* __restrict__ k,
    const float* __restrict__ cs, const float* __restrict__ sn)
{
    const int row = blockIdx.x * 8 + (threadIdx.x >> 5);
    const int i = threadIdx.x & 31;
    const int t = (row / HH) % TT;
    float* p = (blockIdx.y == 0 ? q : k) + (size_t)row * DD;

    float x1 = p[i];
    float x2 = p[i + 32];
    float c = cs[t * 32 + i];
    float s = sn[t * 32 + i];
    float y1 = x1 * c + x2 * s;
    float y2 = -x1 * s + x2 * c;

    float ss = y1 * y1 + y2 * y2;
    #pragma unroll
    for (int o = 16; o; o >>= 1) ss += __shfl_xor_sync(0xffffffffu, ss, o);
    float r = rsqrtf(ss * (1.0f / 64.0f) + EPS);

    p[i]      = y1 * r;
    p[i + 32] = y2 * r;
}

// ---------------------------------------------------------------------------
// Flash attention, tf32 MMA, fragment-layout smem. Br=128, Bc=64, D=64.
// 256 threads (8 warps), each warp owns 16 query rows.
// ---------------------------------------------------------------------------
__global__ __launch_bounds__(256, 2) void flash_tf32(
    const float* __restrict__ q, const float* __restrict__ kk,
    const float* __restrict__ vv, float* __restrict__ y)
{
    extern __shared__ float sm[];
    float* QsF = sm;              // 8 mtiles x 8 kc x 32 x 4 = 8192
    float* KsF = sm + 8192;       // 8 ntiles x 8 kc x 32 x 2 = 4096
    float* PsF = sm + 12288;      // 8 mtiles x 8 kc x 32 x 4 = 8192
    float* VtF = sm + 20480;      // 8 ntiles x 8 kc x 32 x 2 = 4096

    const int tid = threadIdx.x;
    const int wid = tid >> 5;
    const int lane = tid & 31;
    const int g = lane >> 2, tg = lane & 3;

    const int bh = blockIdx.y;
    const size_t base = (size_t)(bh / HH) * TT * CC + (size_t)(bh % HH) * DD;
    const int q0 = blockIdx.x * 128;

    // Load Q tile (128x64) into A-fragment layout, fold 1/sqrt(D)
    #pragma unroll
    for (int t = 0; t < 8; t++) {
        int idx = tid + t * 256;
        int r = idx >> 4, c4 = (idx & 15) << 2;
        float4 v = *(const float4*)&q[base + (size_t)(q0 + r) * CC + c4];
        int reg = (((r & 15) >= 8) ? 1 : 0) + ((c4 & 4) >> 1);
        float* bse = &QsF[(((r >> 4) * 8 + (c4 >> 3)) * 32 + (r & 7) * 4) * 4 + reg];
        bse[0]  = to_tf32(v.x * 0.125f); bse[4]  = to_tf32(v.y * 0.125f);
        bse[8]  = to_tf32(v.z * 0.125f); bse[12] = to_tf32(v.w * 0.125f);
    }

    float mrow[2] = {-1e30f, -1e30f};
    float lrow[2] = {0.0f, 0.0f};
    float oacc[8][4] = {};

    for (int j0 = 0; j0 < TT; j0 += 64) {
        __syncthreads();   // previous PV done reading KsF/VtF
        // Load K into B-frag (n=key, k=d); V into B-frag (n=d, k=key)
        #pragma unroll
        for (int t = 0; t < 4; t++) {
            int idx = tid + t * 256;
            int r = idx >> 4, c4 = (idx & 15) << 2;   // r: key row, c4: d
            size_t ga = base + (size_t)(j0 + r) * CC + c4;
            float4 kv = *(const float4*)&kk[ga];
            float* kb = &KsF[(((r >> 3) * 8 + (c4 >> 3)) * 32 + (r & 7) * 4) * 2 + ((c4 & 4) >> 2)];
            kb[0] = to_tf32(kv.x); kb[2] = to_tf32(kv.y);
            kb[4] = to_tf32(kv.z); kb[6] = to_tf32(kv.w);

            float4 vb = *(const float4*)&vv[ga];
            int vreg = ((r & 7) >= 4) ? 1 : 0;
            float* vbs = &VtF[(((c4 >> 3) * 8 + (r >> 3)) * 32 + (c4 & 7) * 4 + (r & 3)) * 2 + vreg];
            vbs[0]  = to_tf32(vb.x); vbs[8]  = to_tf32(vb.y);
            vbs[16] = to_tf32(vb.z); vbs[24] = to_tf32(vb.w);
        }
        __syncthreads();

        // S = (Q*scale) K^T
        float sacc[8][4] = {};
        #pragma unroll
        for (int kc = 0; kc < 8; kc++) {
            uint4 af = *(const uint4*)&QsF[((wid * 8 + kc) * 32 + lane) * 4];
            #pragma unroll
            for (int ni = 0; ni < 8; ni++) {
                uint2 bf = *(const uint2*)&KsF[((ni * 8 + kc) * 32 + lane) * 2];
                mma_tf32(sacc[ni], (const uint32_t*)&af, (const uint32_t*)&bf);
            }
        }

        // Online softmax (rows g, g+8 of this warp's 16-row tile)
        float rmax[2] = {-1e30f, -1e30f};
        #pragma unroll
        for (int ni = 0; ni < 8; ni++) {
            rmax[0] = fmaxf(rmax[0], fmaxf(sacc[ni][0], sacc[ni][1]));
            rmax[1] = fmaxf(rmax[1], fmaxf(sacc[ni][2], sacc[ni][3]));
        }
        #pragma unroll
        for (int o = 1; o <= 2; o <<= 1) {
            rmax[0] = fmaxf(rmax[0], __shfl_xor_sync(0xffffffffu, rmax[0], o));
            rmax[1] = fmaxf(rmax[1], __shfl_xor_sync(0xffffffffu, rmax[1], o));
        }
        float nm0 = fmaxf(mrow[0], rmax[0]);
        float nm1 = fmaxf(mrow[1], rmax[1]);
        float alpha0 = __expf(mrow[0] - nm0);
        float alpha1 = __expf(mrow[1] - nm1);

        // exp + write P directly in A-fragment layout
        const int lane0 = g * 4 + ((2 * tg) & 3);
        const int regb = (tg >= 2) ? 2 : 0;
        float rsum[2] = {0.0f, 0.0f};
        #pragma unroll
        for (int ni = 0; ni < 8; ni++) {
            float p0 = __expf(sacc[ni][0] - nm0);
            float p1 = __expf(sacc[ni][1] - nm0);
            float p2 = __expf(sacc[ni][2] - nm1);
            float p3 = __expf(sacc[ni][3] - nm1);
            rsum[0] += p0 + p1;
            rsum[1] += p2 + p3;
            float* pb = &PsF[((wid * 8 + ni) * 32) * 4];
            pb[lane0 * 4 + regb]         = to_tf32(p0);
            pb[(lane0 + 1) * 4 + regb]   = to_tf32(p1);
            pb[lane0 * 4 + regb + 1]     = to_tf32(p2);
            pb[(lane0 + 1) * 4 + regb + 1] = to_tf32(p3);
        }
        #pragma unroll
        for (int o = 1; o <= 2; o <<= 1) {
            rsum[0] += __shfl_xor_sync(0xffffffffu, rsum[0], o);
            rsum[1] += __shfl_xor_sync(0xffffffffu, rsum[1], o);
        }
        lrow[0] = lrow[0] * alpha0 + rsum[0];
        lrow[1] = lrow[1] * alpha1 + rsum[1];
        mrow[0] = nm0;
        mrow[1] = nm1;

        #pragma unroll
        for (int ni = 0; ni < 8; ni++) {
            oacc[ni][0] *= alpha0; oacc[ni][1] *= alpha0;
            oacc[ni][2] *= alpha1; oacc[ni][3] *= alpha1;
        }
        __syncwarp();   // Ps rows are warp-local

        // O += P V
        #pragma unroll
        for (int kc = 0; kc < 8; kc++) {
            uint4 af = *(const uint4*)&PsF[((wid * 8 + kc) * 32 + lane) * 4];
            #pragma unroll
            for (int ni = 0; ni < 8; ni++) {
                uint2 bf = *(const uint2*)&VtF[((ni * 8 + kc) * 32 + lane) * 2];
                mma_tf32(oacc[ni], (const uint32_t*)&af, (const uint32_t*)&bf);
            }
        }
    }

    // Epilogue: normalize by l, write (B,T,H,D)
    float inv0 = 1.0f / lrow[0];
    float inv1 = 1.0f / lrow[1];
    int r0 = q0 + wid * 16 + g;
    #pragma unroll
    for (int ni = 0; ni < 8; ni++) {
        int c = ni * 8 + tg * 2;
        *(float2*)&y[base + (size_t)r0 * CC + c] =
            make_float2(oacc[ni][0] * inv0, oacc[ni][1] * inv0);
        *(float2*)&y[base + (size_t)(r0 + 8) * CC + c] =
            make_float2(oacc[ni][2] * inv1, oacc[ni][3] * inv1);
    }
}

// ---------------------------------------------------------------------------
// Launch
// ---------------------------------------------------------------------------
extern "C" void kernel_launch(void* const* d_in, const int* in_sizes, int n_in,
                              void* d_out, int out_size)
{
    const float* x  = (const float*)d_in[0];
    const float* cs = (const float*)d_in[1];
    const float* sn = (const float*)d_in[2];
    const float* Wq = (const float*)d_in[3];
    const float* Wk = (const float*)d_in[4];
    const float* Wv = (const float*)d_in[5];
    const float* Wo = (const float*)d_in[6];
    float* out = (float*)d_out;

    float *qb, *kb, *vb, *yb;
    cudaGetSymbolAddress((void**)&qb, g_q);
    cudaGetSymbolAddress((void**)&kb, g_k);
    cudaGetSymbolAddress((void**)&vb, g_v);
    cudaGetSymbolAddress((void**)&yb, g_y);

    const int M = BB * TT, N = CC, K = CC;

    // Fused QKV projections
    dim3 qkvgrid(N / GBN, M / GBM, 3);   // (8, 64, 3)
    gemm3_tf32<<<qkvgrid, 256>>>(x, Wq, Wk, Wv, qb, kb, vb, M, N, K);

    dim3 rgrid(BB * TT * HH / 8, 2);
    rope_rms<<<rgrid, 256>>>(qb, kb, cs, sn);

    const int smem = 24576 * sizeof(float);   // 96 KB
    cudaFuncSetAttribute(flash_tf32, cudaFuncAttributeMaxDynamicSharedMemorySize, smem);
    dim3 fgrid(TT / 128, BB * HH);   // (16, 64)
    flash_tf32<<<fgrid, 256, smem>>>(qb, kb, vb, yb);

    dim3 ogrid(N / GBN, M / GBM, 1);     // (8, 64, 1)
    gemm3_tf32<<<ogrid, 256>>>(yb, Wo, Wo, Wo, out, out, out, M, N, K);
}

// round 5
// speedup vs baseline: 1.2890x; 1.2890x over previous
#include <cuda_runtime.h>
#include <cuda_bf16.h>
#include <math.h>
#include <stdint.h>

#define BB 4
#define TT 2048
#define CC 1024
#define HH 16
#define DD 64
#define EPS 1.1920929e-07f

// ---------------------------------------------------------------------------
// Scratch (allocation-free rule)
// ---------------------------------------------------------------------------
__device__ float g_q[BB * TT * CC];
__device__ float g_k[BB * TT * CC];
__device__ float g_v[BB * TT * CC];
__device__ float g_y[BB * TT * CC];
__device__ float g_x[BB * TT * CC];
__device__ float g_w[4 * CC * CC];

// ---------------------------------------------------------------------------
// helpers
// ---------------------------------------------------------------------------
__device__ __forceinline__ float to_tf32(float x) {
    uint32_t u;
    asm("cvt.rna.tf32.f32 %0, %1;" : "=r"(u) : "f"(x));
    return __uint_as_float(u);
}

__device__ __forceinline__ void mma_tf32(float* c, const uint32_t* a, const uint32_t* b) {
    asm volatile(
        "mma.sync.aligned.m16n8k8.row.col.f32.tf32.tf32.f32 "
        "{%0,%1,%2,%3}, {%4,%5,%6,%7}, {%8,%9}, {%0,%1,%2,%3};"
        : "+f"(c[0]), "+f"(c[1]), "+f"(c[2]), "+f"(c[3])
        : "r"(a[0]), "r"(a[1]), "r"(a[2]), "r"(a[3]), "r"(b[0]), "r"(b[1]));
}

__device__ __forceinline__ void cp16(uint32_t dst, const void* src) {
    asm volatile("cp.async.ca.shared.global [%0], [%1], 16;" :: "r"(dst), "l"(src));
}
__device__ __forceinline__ void cp_commit() {
    asm volatile("cp.async.commit_group;");
}
template <int N>
__device__ __forceinline__ void cp_wait() {
    asm volatile("cp.async.wait_group %0;" :: "n"(N));
}

// ---------------------------------------------------------------------------
// Pre-pass: tf32-round (rna) src -> dst
// ---------------------------------------------------------------------------
__global__ __launch_bounds__(256) void round_pass(
    const float* __restrict__ src, float* __restrict__ dst, int n)
{
    int i = (blockIdx.x * 256 + threadIdx.x) * 4;
    if (i < n) {
        float4 v = *(const float4*)(src + i);
        float4 o = make_float4(to_tf32(v.x), to_tf32(v.y), to_tf32(v.z), to_tf32(v.w));
        *(float4*)(dst + i) = o;
    }
}

// ---------------------------------------------------------------------------
// GEMM NT (tf32 MMA): C[m,n] = sum_k A[m,k] * W[n,k]. Inputs pre-rounded.
// 128x128x16 tile, 256 threads (8 warps 2x4), warp tile 64x32.
// cp.async double-buffered staging, padded-row smem (proven layout).
// blockIdx.z selects among up to 3 (W, C) pairs.
// ---------------------------------------------------------------------------
#define GBM 128
#define GBN 128
#define GBK 16
#define GPAD 20

__global__ __launch_bounds__(256, 2) void gemm3_tf32(
    const float* __restrict__ A, const float* __restrict__ Wbase,
    float* __restrict__ C0, float* __restrict__ C1, float* __restrict__ C2,
    int M, int N, int K)
{
    __shared__ float As[2][GBM][GPAD];
    __shared__ float Ws[2][GBN][GPAD];

    const float* W = Wbase + (size_t)blockIdx.z * CC * CC;
    float* Cout    = blockIdx.z == 0 ? C0 : (blockIdx.z == 1 ? C1 : C2);

    const int tid = threadIdx.x;
    const int wid = tid >> 5;
    const int lane = tid & 31;
    const int wm = wid & 1;
    const int wn = wid >> 1;
    const int g = lane >> 2;
    const int tg = lane & 3;

    const int m0 = blockIdx.y * GBM;
    const int n0 = blockIdx.x * GBN;

    const int lr = tid >> 2;          // 0..63
    const int lc = (tid & 3) << 2;    // 0,4,8,12

    const float* a0 = &A[(size_t)(m0 + lr) * K + lc];
    const float* a1 = &A[(size_t)(m0 + lr + 64) * K + lc];
    const float* w0 = &W[(size_t)(n0 + lr) * K + lc];
    const float* w1 = &W[(size_t)(n0 + lr + 64) * K + lc];

    const uint32_t sA = (uint32_t)__cvta_generic_to_shared(&As[0][0][0]);
    const uint32_t sW = (uint32_t)__cvta_generic_to_shared(&Ws[0][0][0]);
    const uint32_t dA0 = sA + ((lr) * GPAD + lc) * 4;
    const uint32_t dA1 = sA + ((lr + 64) * GPAD + lc) * 4;
    const uint32_t dW0 = sW + ((lr) * GPAD + lc) * 4;
    const uint32_t dW1 = sW + ((lr + 64) * GPAD + lc) * 4;
    const uint32_t bufB = GBM * GPAD * 4;   // bytes per buffer

    float acc[4][4][4] = {};

    // prologue: stage tile 0
    cp16(dA0, a0); cp16(dA1, a1);
    cp16(dW0, w0); cp16(dW1, w1);
    cp_commit();

    const int nt = K / GBK;   // 64
    for (int kt = 0; kt < nt; kt++) {
        const int cur = kt & 1;
        if (kt + 1 < nt) {
            const uint32_t off = (cur ^ 1) * bufB;
            const int k1 = (kt + 1) * GBK;
            cp16(dA0 + off, a0 + k1); cp16(dA1 + off, a1 + k1);
            cp16(dW0 + off, w0 + k1); cp16(dW1 + off, w1 + k1);
            cp_commit();
            cp_wait<1>();
        } else {
            cp_wait<0>();
        }
        __syncthreads();

        #pragma unroll
        for (int kc = 0; kc < 2; kc++) {
            const int kk = kc * 8;
            uint32_t af[4][4], bf[4][2];
            #pragma unroll
            for (int mi = 0; mi < 4; mi++) {
                int mb = wm * 64 + mi * 16;
                af[mi][0] = __float_as_uint(As[cur][mb + g    ][kk + tg]);
                af[mi][1] = __float_as_uint(As[cur][mb + g + 8][kk + tg]);
                af[mi][2] = __float_as_uint(As[cur][mb + g    ][kk + tg + 4]);
                af[mi][3] = __float_as_uint(As[cur][mb + g + 8][kk + tg + 4]);
            }
            #pragma unroll
            for (int ni = 0; ni < 4; ni++) {
                int nb = wn * 32 + ni * 8;
                bf[ni][0] = __float_as_uint(Ws[cur][nb + g][kk + tg]);
                bf[ni][1] = __float_as_uint(Ws[cur][nb + g][kk + tg + 4]);
            }
            #pragma unroll
            for (int mi = 0; mi < 4; mi++)
                #pragma unroll
                for (int ni = 0; ni < 4; ni++)
                    mma_tf32(acc[mi][ni], af[mi], bf[ni]);
        }
        __syncthreads();
    }

    #pragma unroll
    for (int mi = 0; mi < 4; mi++) {
        int r = m0 + wm * 64 + mi * 16 + g;
        #pragma unroll
        for (int ni = 0; ni < 4; ni++) {
            int c = n0 + wn * 32 + ni * 8 + tg * 2;
            *(float2*)&Cout[(size_t)r * N + c] =
                make_float2(acc[mi][ni][0], acc[mi][ni][1]);
            *(float2*)&Cout[(size_t)(r + 8) * N + c] =
                make_float2(acc[mi][ni][2], acc[mi][ni][3]);
        }
    }
}

// ---------------------------------------------------------------------------
// RoPE (concat-half) + RMSnorm; emits tf32-rounded values.
// y==0: q (x 0.125 folded), y==1: k, y==2: v (round only).
// ---------------------------------------------------------------------------
__global__ __launch_bounds__(256) void rope_rms(
    float* __restrict__ q, float* __restrict__ k, float* __restrict__ v,
    const float* __restrict__ cs, const float* __restrict__ sn)
{
    const int row = blockIdx.x * 8 + (threadIdx.x >> 5);
    const int i = threadIdx.x & 31;

    if (blockIdx.y == 2) {
        float* p = v + (size_t)row * DD;
        p[i]      = to_tf32(p[i]);
        p[i + 32] = to_tf32(p[i + 32]);
        return;
    }

    const int t = (row / HH) % TT;
    float* p = (blockIdx.y == 0 ? q : k) + (size_t)row * DD;

    float x1 = p[i];
    float x2 = p[i + 32];
    float c = cs[t * 32 + i];
    float s = sn[t * 32 + i];
    float y1 = x1 * c + x2 * s;
    float y2 = -x1 * s + x2 * c;

    float ss = y1 * y1 + y2 * y2;
    #pragma unroll
    for (int o = 16; o; o >>= 1) ss += __shfl_xor_sync(0xffffffffu, ss, o);
    float r = rsqrtf(ss * (1.0f / 64.0f) + EPS);
    if (blockIdx.y == 0) r *= 0.125f;   // fold attention scale into q

    p[i]      = to_tf32(y1 * r);
    p[i + 32] = to_tf32(y2 * r);
}

// ---------------------------------------------------------------------------
// Flash attention, tf32 MMA. Br=128, Bc=64, D=64, 256 threads (8 warps).
// K double-buffered via cp.async; V register-prefetched + transposed STS.
// Inputs pre-rounded (q pre-scaled). Output y tf32-rounded.
// ---------------------------------------------------------------------------
#define FLD 68
#define NJT (TT / 64)

__global__ __launch_bounds__(256) void flash_tf32(
    const float* __restrict__ q, const float* __restrict__ kk,
    const float* __restrict__ vv, float* __restrict__ y)
{
    extern __shared__ float sm[];
    float* Qs = sm;                       // 128 x 68
    float* Ks = sm + 128 * FLD;           // 2 x 64 x 68
    float* Vt = sm + 256 * FLD;           // 64 x 68  (d-major)
    float* Ps = sm + 320 * FLD;           // 128 x 68

    const int tid = threadIdx.x;
    const int wid = tid >> 5;
    const int lane = tid & 31;
    const int g = lane >> 2, tg = lane & 3;

    const int bh = blockIdx.y;
    const size_t base = (size_t)(bh / HH) * TT * CC + (size_t)(bh % HH) * DD;
    const int q0 = blockIdx.x * 128;

    const int c4 = (tid & 15) << 2;   // 0..60
    const int rr = tid >> 4;          // 0..15

    const uint32_t sQ = (uint32_t)__cvta_generic_to_shared(Qs);
    const uint32_t sK = (uint32_t)__cvta_generic_to_shared(Ks);

    // Q tile (128x64) via cp.async
    #pragma unroll
    for (int t = 0; t < 8; t++) {
        int r = rr + t * 16;
        cp16(sQ + ((r * FLD + c4) * 4), &q[base + (size_t)(q0 + r) * CC + c4]);
    }
    // K tile 0 via cp.async (group 1)
    cp_commit();
    #pragma unroll
    for (int t = 0; t < 4; t++) {
        int r = rr + t * 16;
        cp16(sK + ((r * FLD + c4) * 4), &kk[base + (size_t)r * CC + c4]);
    }
    cp_commit();
    // V tile 0 into registers
    float4 vr[4];
    #pragma unroll
    for (int t = 0; t < 4; t++)
        vr[t] = *(const float4*)&vv[base + (size_t)(rr + t * 16) * CC + c4];

    float mrow[2] = {-1e30f, -1e30f};
    float lrow[2] = {0.0f, 0.0f};
    float oacc[8][4] = {};
    const int mb = wid * 16;

    for (int jt = 0; jt < NJT; jt++) {
        const int cur = jt & 1;
        // store V regs transposed: Vt[d][s], d-major stride FLD
        #pragma unroll
        for (int t = 0; t < 4; t++) {
            int r = rr + t * 16;
            Vt[(c4 + 0) * FLD + r] = vr[t].x;
            Vt[(c4 + 1) * FLD + r] = vr[t].y;
            Vt[(c4 + 2) * FLD + r] = vr[t].z;
            Vt[(c4 + 3) * FLD + r] = vr[t].w;
        }
        if (jt + 1 < NJT) {
            const int j1 = (jt + 1) * 64;
            #pragma unroll
            for (int t = 0; t < 4; t++) {
                int r = rr + t * 16;
                cp16(sK + (((cur ^ 1) * 64 + r) * FLD + c4) * 4,
                     &kk[base + (size_t)(j1 + r) * CC + c4]);
            }
            cp_commit();
            cp_wait<1>();
        } else {
            cp_wait<0>();
        }
        __syncthreads();

        // prefetch next V during compute
        if (jt + 1 < NJT) {
            const int j1 = (jt + 1) * 64;
            #pragma unroll
            for (int t = 0; t < 4; t++)
                vr[t] = *(const float4*)&vv[base + (size_t)(j1 + rr + t * 16) * CC + c4];
        }

        // S = (Q*scale) K^T
        float sacc[8][4] = {};
        #pragma unroll
        for (int ks = 0; ks < 64; ks += 8) {
            uint32_t af[4];
            af[0] = __float_as_uint(Qs[(mb + g    ) * FLD + ks + tg]);
            af[1] = __float_as_uint(Qs[(mb + g + 8) * FLD + ks + tg]);
            af[2] = __float_as_uint(Qs[(mb + g    ) * FLD + ks + tg + 4]);
            af[3] = __float_as_uint(Qs[(mb + g + 8) * FLD + ks + tg + 4]);
            #pragma unroll
            for (int ni = 0; ni < 8; ni++) {
                const float* kbp = &Ks[(cur * 64 + ni * 8 + g) * FLD + ks + tg];
                uint32_t bf[2];
                bf[0] = __float_as_uint(kbp[0]);
                bf[1] = __float_as_uint(kbp[4]);
                mma_tf32(sacc[ni], af, bf);
            }
        }

        // Online softmax
        float rmax[2] = {-1e30f, -1e30f};
        #pragma unroll
        for (int ni = 0; ni < 8; ni++) {
            rmax[0] = fmaxf(rmax[0], fmaxf(sacc[ni][0], sacc[ni][1]));
            rmax[1] = fmaxf(rmax[1], fmaxf(sacc[ni][2], sacc[ni][3]));
        }
        #pragma unroll
        for (int o = 1; o <= 2; o <<= 1) {
            rmax[0] = fmaxf(rmax[0], __shfl_xor_sync(0xffffffffu, rmax[0], o));
            rmax[1] = fmaxf(rmax[1], __shfl_xor_sync(0xffffffffu, rmax[1], o));
        }
        float nm0 = fmaxf(mrow[0], rmax[0]);
        float nm1 = fmaxf(mrow[1], rmax[1]);
        float alpha0 = __expf(mrow[0] - nm0);
        float alpha1 = __expf(mrow[1] - nm1);

        float rsum[2] = {0.0f, 0.0f};
        #pragma unroll
        for (int ni = 0; ni < 8; ni++) {
            float p0 = __expf(sacc[ni][0] - nm0);
            float p1 = __expf(sacc[ni][1] - nm0);
            float p2 = __expf(sacc[ni][2] - nm1);
            float p3 = __expf(sacc[ni][3] - nm1);
            rsum[0] += p0 + p1;
            rsum[1] += p2 + p3;
            int c = ni * 8 + tg * 2;
            Ps[(mb + g    ) * FLD + c]     = to_tf32(p0);
            Ps[(mb + g    ) * FLD + c + 1] = to_tf32(p1);
            Ps[(mb + g + 8) * FLD + c]     = to_tf32(p2);
            Ps[(mb + g + 8) * FLD + c + 1] = to_tf32(p3);
        }
        #pragma unroll
        for (int o = 1; o <= 2; o <<= 1) {
            rsum[0] += __shfl_xor_sync(0xffffffffu, rsum[0], o);
            rsum[1] += __shfl_xor_sync(0xffffffffu, rsum[1], o);
        }
        lrow[0] = lrow[0] * alpha0 + rsum[0];
        lrow[1] = lrow[1] * alpha1 + rsum[1];
        mrow[0] = nm0;
        mrow[1] = nm1;

        #pragma unroll
        for (int ni = 0; ni < 8; ni++) {
            oacc[ni][0] *= alpha0; oacc[ni][1] *= alpha0;
            oacc[ni][2] *= alpha1; oacc[ni][3] *= alpha1;
        }
        __syncwarp();   // Ps rows are warp-local

        // O += P V
        #pragma unroll
        for (int ks = 0; ks < 64; ks += 8) {
            uint32_t af[4];
            af[0] = __float_as_uint(Ps[(mb + g    ) * FLD + ks + tg]);
            af[1] = __float_as_uint(Ps[(mb + g + 8) * FLD + ks + tg]);
            af[2] = __float_as_uint(Ps[(mb + g    ) * FLD + ks + tg + 4]);
            af[3] = __float_as_uint(Ps[(mb + g + 8) * FLD + ks + tg + 4]);
            #pragma unroll
            for (int ni = 0; ni < 8; ni++) {
                const float* vbp = &Vt[(ni * 8 + g) * FLD + ks + tg];
                uint32_t bf[2];
                bf[0] = __float_as_uint(vbp[0]);
                bf[1] = __float_as_uint(vbp[4]);
                mma_tf32(oacc[ni], af, bf);
            }
        }
        __syncthreads();   // done reading Ks[cur] / Vt before overwrite
    }

    // Epilogue: normalize, round (o-proj consumes pre-rounded), write
    float inv0 = 1.0f / lrow[0];
    float inv1 = 1.0f / lrow[1];
    int r0 = q0 + mb + g;
    #pragma unroll
    for (int ni = 0; ni < 8; ni++) {
        int c = ni * 8 + tg * 2;
        *(float2*)&y[base + (size_t)r0 * CC + c] =
            make_float2(to_tf32(oacc[ni][0] * inv0), to_tf32(oacc[ni][1] * inv0));
        *(float2*)&y[base + (size_t)(r0 + 8) * CC + c] =
            make_float2(to_tf32(oacc[ni][2] * inv1), to_tf32(oacc[ni][3] * inv1));
    }
}

// ---------------------------------------------------------------------------
// Launch
// ---------------------------------------------------------------------------
extern "C" void kernel_launch(void* const* d_in, const int* in_sizes, int n_in,
                              void* d_out, int out_size)
{
    const float* x  = (const float*)d_in[0];
    const float* cs = (const float*)d_in[1];
    const float* sn = (const float*)d_in[2];
    const float* Wq = (const float*)d_in[3];
    const float* Wk = (const float*)d_in[4];
    const float* Wv = (const float*)d_in[5];
    const float* Wo = (const float*)d_in[6];
    float* out = (float*)d_out;

    float *qb, *kb, *vb, *yb, *xb, *wb;
    cudaGetSymbolAddress((void**)&qb, g_q);
    cudaGetSymbolAddress((void**)&kb, g_k);
    cudaGetSymbolAddress((void**)&vb, g_v);
    cudaGetSymbolAddress((void**)&yb, g_y);
    cudaGetSymbolAddress((void**)&xb, g_x);
    cudaGetSymbolAddress((void**)&wb, g_w);

    const int M = BB * TT, N = CC, K = CC;
    const int NX = BB * TT * CC;     // 8M
    const int NW = CC * CC;          // 1M

    // Pre-round inputs (rna) into scratch
    round_pass<<<NX / 1024, 256>>>(x, xb, NX);
    round_pass<<<NW / 1024, 256>>>(Wq, wb + 0 * NW, NW);
    round_pass<<<NW / 1024, 256>>>(Wk, wb + 1 * NW, NW);
    round_pass<<<NW / 1024, 256>>>(Wv, wb + 2 * NW, NW);
    round_pass<<<NW / 1024, 256>>>(Wo, wb + 3 * NW, NW);

    // Fused QKV projections
    dim3 qkvgrid(N / GBN, M / GBM, 3);   // (8, 64, 3)
    gemm3_tf32<<<qkvgrid, 256>>>(xb, wb, qb, kb, vb, M, N, K);

    // RoPE + RMSnorm (+v rounding)
    dim3 rgrid(BB * TT * HH / 8, 3);
    rope_rms<<<rgrid, 256>>>(qb, kb, vb, cs, sn);

    // Flash attention
    const int smem = (448 * FLD) * sizeof(float);   // ~119 KB
    cudaFuncSetAttribute(flash_tf32, cudaFuncAttributeMaxDynamicSharedMemorySize, smem);
    dim3 fgrid(TT / 128, BB * HH);   // (16, 64)
    flash_tf32<<<fgrid, 256, smem>>>(qb, kb, vb, yb);

    // Output projection
    dim3 ogrid(N / GBN, M / GBM, 1);
    gemm3_tf32<<<ogrid, 256>>>(yb, wb + 3 * NW, out, out, out, M, N, K);
}